// round 2
// baseline (speedup 1.0000x reference)
#include <cuda_runtime.h>
#include <cuda_bf16.h>

// Problem constants: b=4, t=10, h=w=256, dim_ae=32
#define HH 256
#define WW 256
#define HW (HH * WW)

// Scratch (allocation-free rule: __device__ globals)
__device__ float g_p1[4 * 32 * HW];   // conv1 out
__device__ float g_p2[4 * 64 * HW];   // conv2 out
__device__ float g_pm[4 * 60 * HW];   // conv3 out (params)

// ---------------------------------------------------------------------------
// Direct 3x3 SAME conv, NCHW. Block = 16x16 threads -> 32x32 spatial tile,
// 16 output channels per block. Each thread: 2x2 pixels x 16 couts = 64 accs.
// Input channels processed in chunks of 4 through shared memory.
// Out-of-range cin/cout are zero-filled in smem so compute loops are
// unconditional (zero weights contribute zero).
// ---------------------------------------------------------------------------
template <int CIN, int COUT, bool RELU>
__global__ __launch_bounds__(256, 2)
void conv3x3_kernel(const float* __restrict__ in, const float* __restrict__ wt,
                    float* __restrict__ out) {
    constexpr int CT = 16;            // couts per block
    constexpr int CC = 4;             // cin chunk
    constexpr int TS = 32;            // spatial tile
    constexpr int IT = TS + 2;        // 34 (haloed)
    constexpr int BPC = (COUT + CT - 1) / CT;

    __shared__ float s_in[CC][IT][IT];
    __shared__ float s_w[CT][CC][9];

    const int tx = threadIdx.x, ty = threadIdx.y;
    const int tid = ty * 16 + tx;
    const int bx = blockIdx.x * TS, by = blockIdx.y * TS;
    const int cob = (blockIdx.z % BPC) * CT;
    const int n = blockIdx.z / BPC;

    const float* in_n = in + (size_t)n * CIN * HW;

    float acc[CT][2][2];
#pragma unroll
    for (int c = 0; c < CT; c++)
#pragma unroll
        for (int i = 0; i < 2; i++)
#pragma unroll
            for (int j = 0; j < 2; j++) acc[c][i][j] = 0.f;

    for (int c0 = 0; c0 < CIN; c0 += CC) {
        __syncthreads();
        // weights for this chunk (zero-fill out of range)
        for (int i = tid; i < CT * CC * 9; i += 256) {
            int ct = i / (CC * 9);
            int rem = i - ct * (CC * 9);
            int cc = rem / 9, k = rem - cc * 9;
            int co = cob + ct, ci = c0 + cc;
            float v = 0.f;
            if (co < COUT && ci < CIN) v = wt[((size_t)co * CIN + ci) * 9 + k];
            s_w[ct][cc][k] = v;
        }
        // haloed input tile for this chunk (zero padding + zero-fill extra cin)
        for (int i = tid; i < CC * IT * IT; i += 256) {
            int cc = i / (IT * IT);
            int rem = i - cc * (IT * IT);
            int r = rem / IT, cl = rem - r * IT;
            int ci = c0 + cc;
            int gy = by + r - 1, gx = bx + cl - 1;
            float v = 0.f;
            if (ci < CIN && (unsigned)gy < HH && (unsigned)gx < WW) {
                v = in_n[(size_t)ci * HW + gy * WW + gx];
                if (RELU) v = fmaxf(v, 0.f);
            }
            s_in[cc][r][cl] = v;
        }
        __syncthreads();

#pragma unroll
        for (int cc = 0; cc < CC; cc++) {
            float r[4][4];
#pragma unroll
            for (int i = 0; i < 4; i++)
#pragma unroll
                for (int j = 0; j < 4; j++)
                    r[i][j] = s_in[cc][ty * 2 + i][tx * 2 + j];
#pragma unroll
            for (int ct = 0; ct < CT; ct++) {
                float wk[9];
#pragma unroll
                for (int k = 0; k < 9; k++) wk[k] = s_w[ct][cc][k];
#pragma unroll
                for (int dy = 0; dy < 3; dy++)
#pragma unroll
                    for (int dx = 0; dx < 3; dx++) {
                        const float wv = wk[dy * 3 + dx];
                        acc[ct][0][0] = fmaf(wv, r[dy][dx], acc[ct][0][0]);
                        acc[ct][0][1] = fmaf(wv, r[dy][dx + 1], acc[ct][0][1]);
                        acc[ct][1][0] = fmaf(wv, r[dy + 1][dx], acc[ct][1][0]);
                        acc[ct][1][1] = fmaf(wv, r[dy + 1][dx + 1], acc[ct][1][1]);
                    }
            }
        }
    }

    const int oy = by + ty * 2, ox = bx + tx * 2;
#pragma unroll
    for (int ct = 0; ct < CT; ct++) {
        int co = cob + ct;
        if (co < COUT) {
            float* op = out + ((size_t)n * COUT + co) * HW + (size_t)oy * WW + ox;
            op[0] = acc[ct][0][0];
            op[1] = acc[ct][0][1];
            op[WW] = acc[ct][1][0];
            op[WW + 1] = acc[ct][1][1];
        }
    }
}

// ---------------------------------------------------------------------------
// Fused guide/PAC epilogue.
// For output frame j in [0,8]: t = j+1. Reads 6 params channels, builds the
// per-pixel 3x3 kernel, contracts with pac_w * x-neighborhood (zero padded).
// Frame j == 9 is written as zeros (d_out is poisoned).
// ---------------------------------------------------------------------------
__device__ __forceinline__ float softplus10(float p) {
    float z = 10.f * p;
    return (fmaxf(z, 0.f) + log1pf(__expf(-fabsf(z)))) * 0.1f;
}

__global__ __launch_bounds__(256)
void fuse_kernel(const float* __restrict__ x, const float* __restrict__ params,
                 const float* __restrict__ pw, const float* __restrict__ pb,
                 float* __restrict__ out) {
    const int gx = blockIdx.x * 32 + threadIdx.x;
    const int gy = blockIdx.y * 8 + threadIdx.y;
    const int z = blockIdx.z;
    const int j = z % 10, n = z / 10;
    const size_t opix = (((size_t)n * 10 + j) * HH + gy) * WW + gx;
    if (j == 9) { out[opix] = 0.f; return; }
    const int t = j + 1;

    const float* pbase = params + (size_t)n * 60 * HW + (size_t)gy * WW + gx;
    const float kap = softplus10(pbase[(size_t)(t) * HW]);
    const float m1d = pbase[(size_t)(10 + t) * HW];
    const float m2d = pbase[(size_t)(20 + t) * HW];
    const float gam = softplus10(pbase[(size_t)(30 + t) * HW]);
    const float vx = pbase[(size_t)(40 + t) * HW];
    const float vy = pbase[(size_t)(50 + t) * HW];

    const float H11 = gam + vx * vx;
    const float H22 = gam + vy * vy;
    const float H12 = vx * vy;
    const float iH11 = 1.f / H11;
    const float iH22 = 1.f / H22;

    float wk[9];
    wk[0] = -0.5f * H12;
    wk[1] = -iH22 + m1d;
    wk[2] = 0.5f * H12;
    wk[3] = -iH11 - m2d;
    wk[4] = kap + 2.f * H11 + 2.f * H22 + 1.f;
    wk[5] = -iH11 + m2d;
    wk[6] = 0.5f * H12;
    wk[7] = -iH22 - m1d;
    wk[8] = -0.5f * H12;

    const float* xf = x + ((size_t)n * 10 + t) * HW;
    float s = 0.f;
#pragma unroll
    for (int d = 0; d < 3; d++)
#pragma unroll
        for (int e = 0; e < 3; e++) {
            const int yy = gy + d - 1, xx = gx + e - 1;
            float xv = 0.f;
            if ((unsigned)yy < HH && (unsigned)xx < WW) xv = __ldg(xf + (size_t)yy * WW + xx);
            s = fmaf(__ldg(pw + d * 3 + e) * wk[d * 3 + e], xv, s);
        }
    out[opix] = s + __ldg(pb);
}

extern "C" void kernel_launch(void* const* d_in, const int* in_sizes, int n_in,
                              void* d_out, int out_size) {
    (void)in_sizes; (void)n_in; (void)out_size;
    const float* x  = (const float*)d_in[0];
    const float* w1 = (const float*)d_in[1];
    const float* w2 = (const float*)d_in[2];
    const float* w3 = (const float*)d_in[3];
    const float* pw = (const float*)d_in[4];
    const float* pb = (const float*)d_in[5];
    float* out = (float*)d_out;

    float *p1, *p2, *pm;
    cudaGetSymbolAddress((void**)&p1, g_p1);
    cudaGetSymbolAddress((void**)&p2, g_p2);
    cudaGetSymbolAddress((void**)&pm, g_pm);

    const dim3 blk(16, 16);
    // conv1: 10 -> 32 (relu on input), 2 cout-blocks per image
    conv3x3_kernel<10, 32, true><<<dim3(8, 8, 4 * 2), blk>>>(x, w1, p1);
    // conv2: 32 -> 64 (relu on input), 4 cout-blocks
    conv3x3_kernel<32, 64, true><<<dim3(8, 8, 4 * 4), blk>>>(p1, w2, p2);
    // conv3: 64 -> 60 (no relu), ceil(60/16)=4 cout-blocks
    conv3x3_kernel<64, 60, false><<<dim3(8, 8, 4 * 4), blk>>>(p2, w3, pm);
    // fused guide + PAC epilogue (also zeroes frame 9)
    fuse_kernel<<<dim3(8, 32, 40), dim3(32, 8)>>>(x, pm, pw, pb, out);
}